// round 2
// baseline (speedup 1.0000x reference)
#include <cuda_runtime.h>

#define NN 100000
#define FF 64
#define HH 128
#define CC 10
#define EE 1600000

// ---------------- scratch (device globals; no runtime allocation) ----------------
__device__ float g_agg[(size_t)NN * HH];
__device__ float g_tmp[(size_t)NN * HH];
__device__ float g_h[(size_t)NN * HH];
__device__ float g_stats[512];  // [0:128)=sum [128:256)=sumsq [256:384)=scale [384:512)=shift
__device__ int g_is64;

// ---------------- packed f32x2 helpers ----------------
__device__ __forceinline__ unsigned long long pk2(float lo, float hi) {
    unsigned long long r;
    asm("mov.b64 %0,{%1,%2};" : "=l"(r) : "f"(lo), "f"(hi));
    return r;
}
__device__ __forceinline__ void upk2(unsigned long long v, float& lo, float& hi) {
    asm("mov.b64 {%0,%1},%2;" : "=f"(lo), "=f"(hi) : "l"(v));
}
__device__ __forceinline__ void ffma2(unsigned long long& d, unsigned long long a, unsigned long long b) {
    asm("fma.rn.f32x2 %0,%1,%2,%0;" : "+l"(d) : "l"(a), "l"(b));
}
__device__ __forceinline__ void red4(float* p, float4 v) {
    asm volatile("red.global.add.v4.f32 [%0], {%1,%2,%3,%4};"
                 :: "l"(p), "f"(v.x), "f"(v.y), "f"(v.z), "f"(v.w) : "memory");
}

// ---------------- edge-index dtype detection (int64 vs int32) ----------------
// int64 indices (< 2^31) have all-zero high words at odd int32 positions.
__global__ void k_detect(const int* __restrict__ ei) {
    if (threadIdx.x == 0) {
        int nz = 0;
        for (int i = 0; i < 1024; i++) nz |= ei[2 * i + 1];
        g_is64 = (nz == 0) ? 1 : 0;
    }
}

// ---------------- simple copy (agg init = self feature) ----------------
__global__ void k_copy(const float4* __restrict__ src, float4* __restrict__ dst, int n) {
    int i = blockIdx.x * blockDim.x + threadIdx.x;
    if (i < n) dst[i] = src[i];
}

// ---------------- edge scatter: agg[dst] += feat[src], CH float4-chunks per row ----------------
template <int CH>
__global__ void k_scatter(const int* __restrict__ ei,
                          const float4* __restrict__ feat,
                          float* __restrict__ agg) {
    int idx = blockIdx.x * blockDim.x + threadIdx.x;
    if (idx >= EE * CH) return;
    int e = idx / CH;          // CH is a power of two -> shift
    int c = idx - e * CH;
    int s, d;
    if (g_is64) { s = ei[2 * e]; d = ei[2 * EE + 2 * e]; }
    else        { s = ei[e];     d = ei[EE + e]; }
    if ((unsigned)s >= NN || (unsigned)d >= NN) return;  // defensive (no-op on valid data)
    float4 v = feat[(long long)s * CH + c];
    red4(agg + ((long long)d * CH + c) * 4, v);
}

// ---------------- fused GEMM + bias (+ReLU): Out[N,128] = act(A[N,K] @ W[K,128] + b) ----------------
// 128x128 block tile, 256 threads, 8x8 microtile, f32x2 packed FFMA.
template <int K, bool RELU>
__global__ void __launch_bounds__(256, 2)
k_gemm(const float* __restrict__ A, const float* __restrict__ W,
       const float* __restrict__ bias, float* __restrict__ Out) {
    extern __shared__ float sm[];
    float* Ws = sm;                                       // [K][128]
    float(*As)[132] = (float(*)[132])(sm + K * 128);      // [16][132] (padded, transposed)

    int tid = threadIdx.x;
    // stage whole W into smem once (row-major K x 128, contiguous)
    {
        const float4* Wg = (const float4*)W;
        float4* Wv = (float4*)Ws;
        #pragma unroll 4
        for (int i = tid; i < K * 32; i += 256) Wv[i] = Wg[i];
    }
    int tx = tid & 15, ty = tid >> 4;
    long long row0 = (long long)blockIdx.x * 128;

    unsigned long long acc[8][4];
    #pragma unroll
    for (int i = 0; i < 8; i++)
        #pragma unroll
        for (int j = 0; j < 4; j++) acc[i][j] = 0ULL;

    for (int k0 = 0; k0 < K; k0 += 16) {
        __syncthreads();  // covers W staging (first iter) and As reuse
        // stage A chunk [128 rows][16 k] transposed into As[k][row]
        for (int i = tid; i < 512; i += 256) {
            int r = i >> 2, c4 = i & 3;
            long long gr = row0 + r;
            float4 v = make_float4(0.f, 0.f, 0.f, 0.f);
            if (gr < NN) v = *(const float4*)(A + gr * K + k0 + c4 * 4);
            int kk = c4 * 4;
            As[kk][r] = v.x; As[kk + 1][r] = v.y; As[kk + 2][r] = v.z; As[kk + 3][r] = v.w;
        }
        __syncthreads();
        #pragma unroll
        for (int k = 0; k < 16; k++) {
            const float4 a03 = *(const float4*)&As[k][ty * 8];
            const float4 a47 = *(const float4*)&As[k][ty * 8 + 4];
            const float4 w03 = *(const float4*)&Ws[(k0 + k) * 128 + tx * 8];
            const float4 w47 = *(const float4*)&Ws[(k0 + k) * 128 + tx * 8 + 4];
            unsigned long long wp[4] = {pk2(w03.x, w03.y), pk2(w03.z, w03.w),
                                        pk2(w47.x, w47.y), pk2(w47.z, w47.w)};
            float av[8] = {a03.x, a03.y, a03.z, a03.w, a47.x, a47.y, a47.z, a47.w};
            #pragma unroll
            for (int i = 0; i < 8; i++) {
                unsigned long long ad = pk2(av[i], av[i]);
                #pragma unroll
                for (int j = 0; j < 4; j++) ffma2(acc[i][j], ad, wp[j]);
            }
        }
    }

    int col0 = tx * 8;
    float bb[8];
    #pragma unroll
    for (int j = 0; j < 8; j++) bb[j] = bias[col0 + j];
    #pragma unroll
    for (int i = 0; i < 8; i++) {
        long long gr = row0 + ty * 8 + i;
        if (gr < NN) {
            float o[8];
            #pragma unroll
            for (int j = 0; j < 4; j++) upk2(acc[i][j], o[2 * j], o[2 * j + 1]);
            #pragma unroll
            for (int j = 0; j < 8; j++) {
                o[j] += bb[j];
                if (RELU) o[j] = fmaxf(o[j], 0.f);
            }
            *(float4*)(Out + gr * 128 + col0)     = make_float4(o[0], o[1], o[2], o[3]);
            *(float4*)(Out + gr * 128 + col0 + 4) = make_float4(o[4], o[5], o[6], o[7]);
        }
    }
}

// ---------------- BatchNorm ----------------
__global__ void k_zero_stats() { g_stats[threadIdx.x] = 0.f; }

__global__ void k_stats(const float* __restrict__ h) {
    int c = threadIdx.x;  // 128 threads = one row, coalesced
    float s = 0.f, q = 0.f;
    for (long long r = blockIdx.x; r < NN; r += gridDim.x) {
        float v = h[r * 128 + c];
        s += v;
        q = fmaf(v, v, q);
    }
    atomicAdd(&g_stats[c], s);
    atomicAdd(&g_stats[128 + c], q);
}

__global__ void k_bnfin(const float* __restrict__ g, const float* __restrict__ b) {
    int c = threadIdx.x;
    float inv = 1.f / (float)NN;
    float mean = g_stats[c] * inv;
    float var = g_stats[128 + c] * inv - mean * mean;
    float rstd = rsqrtf(var + 1e-5f);
    float sc = g[c] * rstd;
    g_stats[256 + c] = sc;
    g_stats[384 + c] = b[c] - mean * sc;
}

// y = relu(x*scale + shift); writes o1, and optionally o2 (= agg init for next conv)
__global__ void k_bnapply(const float4* __restrict__ in, float4* __restrict__ o1, float4* o2) {
    int i = blockIdx.x * blockDim.x + threadIdx.x;
    if (i >= NN * 32) return;
    int c4 = i & 31;
    float4 v = in[i];
    float4 sc = *(const float4*)&g_stats[256 + c4 * 4];
    float4 sh = *(const float4*)&g_stats[384 + c4 * 4];
    v.x = fmaxf(fmaf(v.x, sc.x, sh.x), 0.f);
    v.y = fmaxf(fmaf(v.y, sc.y, sh.y), 0.f);
    v.z = fmaxf(fmaf(v.z, sc.z, sh.z), 0.f);
    v.w = fmaxf(fmaf(v.w, sc.w, sh.w), 0.f);
    o1[i] = v;
    if (o2) o2[i] = v;
}

// ---------------- classifier head: out[N,10] = m[N,128] @ w[128,10] + b ----------------
__global__ void __launch_bounds__(128) k_out(const float* __restrict__ m,
                                             const float* __restrict__ w,
                                             const float* __restrict__ b,
                                             float* __restrict__ out) {
    __shared__ float Wsm[1280];
    __shared__ float Ms[128][33];
    int tid = threadIdx.x;
    for (int i = tid; i < 1280; i += 128) Wsm[i] = w[i];
    long long row0 = (long long)blockIdx.x * 128;
    float acc[10];
    #pragma unroll
    for (int c = 0; c < 10; c++) acc[c] = b[c];
    for (int k0 = 0; k0 < 128; k0 += 32) {
        __syncthreads();
        for (int i = tid; i < 1024; i += 128) {
            int r = i >> 3, c4 = i & 7;
            long long gr = row0 + r;
            float4 v = make_float4(0.f, 0.f, 0.f, 0.f);
            if (gr < NN) v = *(const float4*)(m + gr * 128 + k0 + c4 * 4);
            Ms[r][c4 * 4] = v.x; Ms[r][c4 * 4 + 1] = v.y;
            Ms[r][c4 * 4 + 2] = v.z; Ms[r][c4 * 4 + 3] = v.w;
        }
        __syncthreads();
        #pragma unroll
        for (int kk = 0; kk < 32; kk++) {
            float a = Ms[tid][kk];
            #pragma unroll
            for (int c = 0; c < 10; c++) acc[c] = fmaf(a, Wsm[(k0 + kk) * 10 + c], acc[c]);
        }
    }
    long long gr = row0 + tid;
    if (gr < NN) {
        #pragma unroll
        for (int c = 0; c < 10; c++) out[gr * 10 + c] = acc[c];
    }
}

// ---------------- launch ----------------
extern "C" void kernel_launch(void* const* d_in, const int* in_sizes, int n_in,
                              void* d_out, int out_size) {
    const float* x      = (const float*)d_in[0];
    const int*   ei     = (const int*)d_in[1];
    const float* w1a = (const float*)d_in[2];  const float* b1a = (const float*)d_in[3];
    const float* w1b = (const float*)d_in[4];  const float* b1b = (const float*)d_in[5];
    const float* w2a = (const float*)d_in[6];  const float* b2a = (const float*)d_in[7];
    const float* w2b = (const float*)d_in[8];  const float* b2b = (const float*)d_in[9];
    const float* bn1g = (const float*)d_in[10]; const float* bn1b = (const float*)d_in[11];
    const float* bn2g = (const float*)d_in[12]; const float* bn2b = (const float*)d_in[13];
    const float* mw1 = (const float*)d_in[14]; const float* mb1 = (const float*)d_in[15];
    const float* mw2 = (const float*)d_in[16]; const float* mb2 = (const float*)d_in[17];
    float* out = (float*)d_out;

    float *agg, *tmp, *hh;
    cudaGetSymbolAddress((void**)&agg, g_agg);
    cudaGetSymbolAddress((void**)&tmp, g_tmp);
    cudaGetSymbolAddress((void**)&hh, g_h);

    const int SMEM64  = (64 * 128 + 16 * 132) * 4;   // 41216
    const int SMEM128 = (128 * 128 + 16 * 132) * 4;  // 73984
    cudaFuncSetAttribute(k_gemm<64, true>,   cudaFuncAttributeMaxDynamicSharedMemorySize, SMEM64);
    cudaFuncSetAttribute(k_gemm<128, true>,  cudaFuncAttributeMaxDynamicSharedMemorySize, SMEM128);
    cudaFuncSetAttribute(k_gemm<128, false>, cudaFuncAttributeMaxDynamicSharedMemorySize, SMEM128);

    const int GB = (NN + 127) / 128;  // 782 row blocks

    k_detect<<<1, 32>>>(ei);

    // ---- conv1: agg = x + sum_neighbors(x); h = (relu(agg@w1a+b1a))@w1b+b1b
    k_copy<<<(NN * 16 + 255) / 256, 256>>>((const float4*)x, (float4*)agg, NN * 16);
    k_scatter<16><<<(EE * 16 + 255) / 256, 256>>>(ei, (const float4*)x, agg);
    k_gemm<64, true><<<GB, 256, SMEM64>>>(agg, w1a, b1a, tmp);
    k_gemm<128, false><<<GB, 256, SMEM128>>>(tmp, w1b, b1b, hh);
    // ---- bn1 + relu -> h1 (into tmp for gather, into agg as self-init for conv2)
    k_zero_stats<<<1, 512>>>();
    k_stats<<<512, 128>>>(hh);
    k_bnfin<<<1, 128>>>(bn1g, bn1b);
    k_bnapply<<<(NN * 32 + 255) / 256, 256>>>((const float4*)hh, (float4*)tmp, (float4*)agg);
    // ---- conv2
    k_scatter<32><<<(EE * 32 + 255) / 256, 256>>>(ei, (const float4*)tmp, agg);
    k_gemm<128, true><<<GB, 256, SMEM128>>>(agg, w2a, b2a, hh);
    k_gemm<128, false><<<GB, 256, SMEM128>>>(hh, w2b, b2b, tmp);
    // ---- bn2 + relu -> latent (directly into d_out[0 : N*128))
    k_zero_stats<<<1, 512>>>();
    k_stats<<<512, 128>>>(tmp);
    k_bnfin<<<1, 128>>>(bn2g, bn2b);
    k_bnapply<<<(NN * 32 + 255) / 256, 256>>>((const float4*)tmp, (float4*)out, (float4*)0);
    // ---- classifier: class_out -> d_out[N*128 : N*128+N*10)
    k_gemm<128, true><<<GB, 256, SMEM128>>>(out, mw1, mb1, hh);
    k_out<<<GB, 128>>>(hh, mw2, mb2, out + (long long)NN * 128);
}

// round 4
// speedup vs baseline: 1.2439x; 1.2439x over previous
#include <cuda_runtime.h>
#include <cuda_bf16.h>

#define NN 100000
#define FF 64
#define HH 128
#define CC 10
#define EE 1600000

// ---------------- scratch ----------------
__device__ float g_agg[(size_t)NN * HH];
__device__ float g_tmp[(size_t)NN * HH];
__device__ float g_h[(size_t)NN * HH];
__device__ float g_stats[512];
__device__ int g_is64;

// ---------------- helpers ----------------
__device__ __forceinline__ void red4(float* p, float4 v) {
    asm volatile("red.global.add.v4.f32 [%0], {%1,%2,%3,%4};"
                 :: "l"(p), "f"(v.x), "f"(v.y), "f"(v.z), "f"(v.w) : "memory");
}

// split float into bf16 hi + bf16 lo(residual); return packed pair words via refs
__device__ __forceinline__ void bfsplit(float x, unsigned short& h, unsigned short& l) {
    __nv_bfloat16 hb = __float2bfloat16_rn(x);
    float r = x - __bfloat162float(hb);
    __nv_bfloat16 lb = __float2bfloat16_rn(r);
    h = *(unsigned short*)&hb;
    l = *(unsigned short*)&lb;
}
__device__ __forceinline__ unsigned pck(unsigned short lo, unsigned short hi) {
    return (unsigned)lo | ((unsigned)hi << 16);
}

__device__ __forceinline__ void mma16816(float* d, unsigned a0, unsigned a1, unsigned a2,
                                         unsigned a3, unsigned b0, unsigned b1) {
    asm volatile("mma.sync.aligned.m16n8k16.row.col.f32.bf16.bf16.f32 "
                 "{%0,%1,%2,%3},{%4,%5,%6,%7},{%8,%9},{%0,%1,%2,%3};"
                 : "+f"(d[0]), "+f"(d[1]), "+f"(d[2]), "+f"(d[3])
                 : "r"(a0), "r"(a1), "r"(a2), "r"(a3), "r"(b0), "r"(b1));
}

// ---------------- misc kernels ----------------
__global__ void k_detect(const int* __restrict__ ei) {
    if (threadIdx.x == 0) {
        int nz = 0;
        for (int i = 0; i < 1024; i++) nz |= ei[2 * i + 1];
        g_is64 = (nz == 0) ? 1 : 0;
    }
}
__global__ void k_copy(const float4* __restrict__ src, float4* __restrict__ dst, int n) {
    int i = blockIdx.x * blockDim.x + threadIdx.x;
    if (i < n) dst[i] = src[i];
}

template <int CHN>
__global__ void k_scatter(const int* __restrict__ ei,
                          const float4* __restrict__ feat,
                          float* __restrict__ agg) {
    int idx = blockIdx.x * blockDim.x + threadIdx.x;
    if (idx >= EE * CHN) return;
    int e = idx / CHN;
    int c = idx - e * CHN;
    int s, d;
    if (g_is64) { s = ei[2 * e]; d = ei[2 * EE + 2 * e]; }
    else        { s = ei[e];     d = ei[EE + e]; }
    if ((unsigned)s >= NN || (unsigned)d >= NN) return;
    float4 v = feat[(long long)s * CHN + c];
    red4(agg + ((long long)d * CHN + c) * 4, v);
}

// ---------------- mma.sync bf16-split3 GEMM: Out[N,128] = act(A[N,K]@W[K,128]+b) ----------------
// 256 threads, 128x128 tile, 8 warps (4m x 2n), warp tile 32x64, k-chunk 16.
template <int K, bool RELU>
__global__ void __launch_bounds__(256, 2)
k_mgemm(const float* __restrict__ A, const float* __restrict__ W,
        const float* __restrict__ bias, float* __restrict__ Out) {
    __shared__ unsigned Ash[128][9], Asl[128][9];   // [row][k-pair], pad to 9 words
    __shared__ unsigned Bsh[128][9], Bsl[128][9];   // [n][k-pair]
    __shared__ float sbias[128];

    const int tid = threadIdx.x;
    const int wid = tid >> 5, lane = tid & 31;
    const int wm = wid >> 1, wn = wid & 1;
    const int g = lane >> 2, t = lane & 3;
    const int row0 = blockIdx.x * 128;

    if (tid < 128) sbias[tid] = bias[tid];

    float acc[2][8][4];
    #pragma unroll
    for (int i = 0; i < 2; i++)
        #pragma unroll
        for (int j = 0; j < 8; j++)
            #pragma unroll
            for (int q = 0; q < 4; q++) acc[i][j][q] = 0.f;

    const int CHK = K / 16;
    for (int c = 0; c < CHK; c++) {
        const int k0 = c * 16;
        __syncthreads();
        // ---- stage A chunk [128 rows][16 k] -> hi/lo packed pairs (256 items, 1/thread)
        {
            int r = tid >> 1, half = tid & 1;
            int gr = row0 + r;
            float4 v1 = make_float4(0.f, 0.f, 0.f, 0.f), v2 = v1;
            if (gr < NN) {
                const float* p = A + (size_t)gr * K + k0 + half * 8;
                v1 = *(const float4*)p;
                v2 = *(const float4*)(p + 4);
            }
            float vv[8] = {v1.x, v1.y, v1.z, v1.w, v2.x, v2.y, v2.z, v2.w};
            #pragma unroll
            for (int j = 0; j < 4; j++) {
                unsigned short h0, l0, h1, l1;
                bfsplit(vv[2 * j], h0, l0);
                bfsplit(vv[2 * j + 1], h1, l1);
                Ash[r][half * 4 + j] = pck(h0, h1);
                Asl[r][half * 4 + j] = pck(l0, l1);
            }
        }
        // ---- stage B chunk = W[k0..k0+16)[128] -> [n][k-pair] hi/lo (256 items)
        {
            int kp = tid >> 5, n0 = (tid & 31) * 4;
            const float* p0 = W + (size_t)(k0 + 2 * kp) * 128 + n0;
            float4 r0 = *(const float4*)p0;
            float4 r1 = *(const float4*)(p0 + 128);
            float a0[4] = {r0.x, r0.y, r0.z, r0.w};
            float a1[4] = {r1.x, r1.y, r1.z, r1.w};
            #pragma unroll
            for (int q = 0; q < 4; q++) {
                unsigned short h0, l0, h1, l1;
                bfsplit(a0[q], h0, l0);
                bfsplit(a1[q], h1, l1);
                Bsh[n0 + q][kp] = pck(h0, h1);
                Bsl[n0 + q][kp] = pck(l0, l1);
            }
        }
        __syncthreads();
        // ---- fragments + mma
        unsigned bh[8][2], bl[8][2];
        #pragma unroll
        for (int nt = 0; nt < 8; nt++) {
            int n = wn * 64 + nt * 8 + g;
            bh[nt][0] = Bsh[n][t]; bh[nt][1] = Bsh[n][t + 4];
            bl[nt][0] = Bsl[n][t]; bl[nt][1] = Bsl[n][t + 4];
        }
        #pragma unroll
        for (int mt = 0; mt < 2; mt++) {
            int rb = wm * 32 + mt * 16;
            unsigned ah0 = Ash[rb + g][t],     ah1 = Ash[rb + 8 + g][t];
            unsigned ah2 = Ash[rb + g][t + 4], ah3 = Ash[rb + 8 + g][t + 4];
            unsigned al0 = Asl[rb + g][t],     al1 = Asl[rb + 8 + g][t];
            unsigned al2 = Asl[rb + g][t + 4], al3 = Asl[rb + 8 + g][t + 4];
            #pragma unroll
            for (int nt = 0; nt < 8; nt++) {
                mma16816(acc[mt][nt], ah0, ah1, ah2, ah3, bh[nt][0], bh[nt][1]);
                mma16816(acc[mt][nt], ah0, ah1, ah2, ah3, bl[nt][0], bl[nt][1]);
                mma16816(acc[mt][nt], al0, al1, al2, al3, bh[nt][0], bh[nt][1]);
            }
        }
    }
    // ---- epilogue: bias + relu, direct global stores (float2 per fragment row)
    #pragma unroll
    for (int mt = 0; mt < 2; mt++) {
        #pragma unroll
        for (int nt = 0; nt < 8; nt++) {
            int cc = wn * 64 + nt * 8 + 2 * t;
            float b0 = sbias[cc], b1 = sbias[cc + 1];
            int r0r = row0 + wm * 32 + mt * 16 + g;
            float d0 = acc[mt][nt][0] + b0, d1 = acc[mt][nt][1] + b1;
            float d2 = acc[mt][nt][2] + b0, d3 = acc[mt][nt][3] + b1;
            if (RELU) {
                d0 = fmaxf(d0, 0.f); d1 = fmaxf(d1, 0.f);
                d2 = fmaxf(d2, 0.f); d3 = fmaxf(d3, 0.f);
            }
            if (r0r < NN) *(float2*)(Out + (size_t)r0r * 128 + cc) = make_float2(d0, d1);
            if (r0r + 8 < NN) *(float2*)(Out + (size_t)(r0r + 8) * 128 + cc) = make_float2(d2, d3);
        }
    }
}

// ---------------- BatchNorm ----------------
__global__ void k_zero_stats() { g_stats[threadIdx.x] = 0.f; }

__global__ void k_stats(const float* __restrict__ h) {
    int c = threadIdx.x;
    float s = 0.f, q = 0.f;
    for (long long r = blockIdx.x; r < NN; r += gridDim.x) {
        float v = h[r * 128 + c];
        s += v;
        q = fmaf(v, v, q);
    }
    atomicAdd(&g_stats[c], s);
    atomicAdd(&g_stats[128 + c], q);
}

__global__ void k_bnfin(const float* __restrict__ g, const float* __restrict__ b) {
    int c = threadIdx.x;
    float inv = 1.f / (float)NN;
    float mean = g_stats[c] * inv;
    float var = g_stats[128 + c] * inv - mean * mean;
    float rstd = rsqrtf(var + 1e-5f);
    float sc = g[c] * rstd;
    g_stats[256 + c] = sc;
    g_stats[384 + c] = b[c] - mean * sc;
}

__global__ void k_bnapply(const float4* __restrict__ in, float4* __restrict__ o1, float4* o2) {
    int i = blockIdx.x * blockDim.x + threadIdx.x;
    if (i >= NN * 32) return;
    int c4 = i & 31;
    float4 v = in[i];
    float4 sc = *(const float4*)&g_stats[256 + c4 * 4];
    float4 sh = *(const float4*)&g_stats[384 + c4 * 4];
    v.x = fmaxf(fmaf(v.x, sc.x, sh.x), 0.f);
    v.y = fmaxf(fmaf(v.y, sc.y, sh.y), 0.f);
    v.z = fmaxf(fmaf(v.z, sc.z, sh.z), 0.f);
    v.w = fmaxf(fmaf(v.w, sc.w, sh.w), 0.f);
    o1[i] = v;
    if (o2) o2[i] = v;
}

// ---------------- classifier head ----------------
__global__ void __launch_bounds__(128) k_out(const float* __restrict__ m,
                                             const float* __restrict__ w,
                                             const float* __restrict__ b,
                                             float* __restrict__ out) {
    __shared__ float Wsm[1280];
    __shared__ float Ms[128][33];
    int tid = threadIdx.x;
    for (int i = tid; i < 1280; i += 128) Wsm[i] = w[i];
    long long row0 = (long long)blockIdx.x * 128;
    float acc[10];
    #pragma unroll
    for (int c = 0; c < 10; c++) acc[c] = b[c];
    for (int k0 = 0; k0 < 128; k0 += 32) {
        __syncthreads();
        for (int i = tid; i < 1024; i += 128) {
            int r = i >> 3, c4 = i & 7;
            long long gr = row0 + r;
            float4 v = make_float4(0.f, 0.f, 0.f, 0.f);
            if (gr < NN) v = *(const float4*)(m + gr * 128 + k0 + c4 * 4);
            Ms[r][c4 * 4] = v.x; Ms[r][c4 * 4 + 1] = v.y;
            Ms[r][c4 * 4 + 2] = v.z; Ms[r][c4 * 4 + 3] = v.w;
        }
        __syncthreads();
        #pragma unroll
        for (int kk = 0; kk < 32; kk++) {
            float a = Ms[tid][kk];
            #pragma unroll
            for (int c = 0; c < 10; c++) acc[c] = fmaf(a, Wsm[(k0 + kk) * 10 + c], acc[c]);
        }
    }
    long long gr = row0 + tid;
    if (gr < NN) {
        #pragma unroll
        for (int c = 0; c < 10; c++) out[gr * 10 + c] = acc[c];
    }
}

// ---------------- launch ----------------
extern "C" void kernel_launch(void* const* d_in, const int* in_sizes, int n_in,
                              void* d_out, int out_size) {
    const float* x    = (const float*)d_in[0];
    const int*   ei   = (const int*)d_in[1];
    const float* w1a = (const float*)d_in[2];  const float* b1a = (const float*)d_in[3];
    const float* w1b = (const float*)d_in[4];  const float* b1b = (const float*)d_in[5];
    const float* w2a = (const float*)d_in[6];  const float* b2a = (const float*)d_in[7];
    const float* w2b = (const float*)d_in[8];  const float* b2b = (const float*)d_in[9];
    const float* bn1g = (const float*)d_in[10]; const float* bn1b = (const float*)d_in[11];
    const float* bn2g = (const float*)d_in[12]; const float* bn2b = (const float*)d_in[13];
    const float* mw1 = (const float*)d_in[14]; const float* mb1 = (const float*)d_in[15];
    const float* mw2 = (const float*)d_in[16]; const float* mb2 = (const float*)d_in[17];
    float* out = (float*)d_out;

    float *agg, *tmp, *hh;
    cudaGetSymbolAddress((void**)&agg, g_agg);
    cudaGetSymbolAddress((void**)&tmp, g_tmp);
    cudaGetSymbolAddress((void**)&hh, g_h);

    const int GB = (NN + 127) / 128;  // 782

    k_detect<<<1, 32>>>(ei);

    // conv1
    k_copy<<<(NN * 16 + 255) / 256, 256>>>((const float4*)x, (float4*)agg, NN * 16);
    k_scatter<16><<<(EE * 16 + 255) / 256, 256>>>(ei, (const float4*)x, agg);
    k_mgemm<64, true><<<GB, 256>>>(agg, w1a, b1a, tmp);
    k_mgemm<128, false><<<GB, 256>>>(tmp, w1b, b1b, hh);
    // bn1
    k_zero_stats<<<1, 512>>>();
    k_stats<<<512, 128>>>(hh);
    k_bnfin<<<1, 128>>>(bn1g, bn1b);
    k_bnapply<<<(NN * 32 + 255) / 256, 256>>>((const float4*)hh, (float4*)tmp, (float4*)agg);
    // conv2
    k_scatter<32><<<(EE * 32 + 255) / 256, 256>>>(ei, (const float4*)tmp, agg);
    k_mgemm<128, true><<<GB, 256>>>(agg, w2a, b2a, hh);
    k_mgemm<128, false><<<GB, 256>>>(hh, w2b, b2b, tmp);
    // bn2 -> latent in d_out
    k_zero_stats<<<1, 512>>>();
    k_stats<<<512, 128>>>(tmp);
    k_bnfin<<<1, 128>>>(bn2g, bn2b);
    k_bnapply<<<(NN * 32 + 255) / 256, 256>>>((const float4*)tmp, (float4*)out, (float4*)0);
    // classifier
    k_mgemm<128, true><<<GB, 256>>>(out, mw1, mb1, hh);
    k_out<<<GB, 128>>>(hh, mw2, mb2, out + (long long)NN * 128);
}